// round 11
// baseline (speedup 1.0000x reference)
#include <cuda_runtime.h>
#include <cstdint>

// Embedding gather: out[token, :] = embedding[input_ids[token], :]
// input_ids: [4096] i32, embedding: [32000,1024] f32, out: [4096,1024] f32
//
// Fine-grained variant: 2048 CTAs x 128 threads, 2 tokens/CTA.
//  - 128-thread CTAs = 2x more placement units for the GigaThread engine
//    (faster SM fill during ramp, finer tail quantization) and a shorter
//    per-CTA dependent chain (one int2 id load at the head).
//  - 256-bit v8.f32 ops (best ncu so far): each thread covers 32 B of each
//    of the CTA's 2 rows -> 2 independent LDG.256 (MLP=2) + 2 STG.256,
//    16 data regs, no launch_bounds cap needed.

static constexpr int ROW_FLOATS     = 1024;
static constexpr int TOKENS_PER_CTA = 2;

struct alignas(32) f32x8 { float v[8]; };

__device__ __forceinline__ f32x8 ldg256(const float* p) {
    f32x8 r;
    asm volatile("ld.global.nc.v8.f32 {%0,%1,%2,%3,%4,%5,%6,%7}, [%8];"
                 : "=f"(r.v[0]), "=f"(r.v[1]), "=f"(r.v[2]), "=f"(r.v[3]),
                   "=f"(r.v[4]), "=f"(r.v[5]), "=f"(r.v[6]), "=f"(r.v[7])
                 : "l"(p));
    return r;
}
__device__ __forceinline__ void stg256(float* p, const f32x8& r) {
    asm volatile("st.global.v8.f32 [%0], {%1,%2,%3,%4,%5,%6,%7,%8};"
                 :: "l"(p),
                    "f"(r.v[0]), "f"(r.v[1]), "f"(r.v[2]), "f"(r.v[3]),
                    "f"(r.v[4]), "f"(r.v[5]), "f"(r.v[6]), "f"(r.v[7])
                 : "memory");
}

__global__ void __launch_bounds__(128)
embed_gather_v8f(const int2* __restrict__ ids2,
                 const float* __restrict__ emb,
                 float* __restrict__ out,
                 int n_tokens)
{
    const int off  = threadIdx.x * 8;            // float offset within row
    const int base = blockIdx.x * TOKENS_PER_CTA;

    // Both token ids in one 8-byte broadcast load.
    int2 id = ids2[blockIdx.x];

    // Two independent 256-bit row loads (different rows -> MLP=2).
    f32x8 v0 = ldg256(emb + (size_t)id.x * ROW_FLOATS + off);
    f32x8 v1 = ldg256(emb + (size_t)id.y * ROW_FLOATS + off);

    float* dst = out + (size_t)base * ROW_FLOATS + off;
    stg256(dst,              v0);
    stg256(dst + ROW_FLOATS, v1);
}

extern "C" void kernel_launch(void* const* d_in, const int* in_sizes, int n_in,
                              void* d_out, int out_size)
{
    const int2*  ids2 = (const int2*)d_in[0];
    const float* emb  = (const float*)d_in[1];
    float*       out  = (float*)d_out;

    int n_tokens = in_sizes[0];               // 4096 (divisible by 2)
    int grid = n_tokens / TOKENS_PER_CTA;     // 2048
    embed_gather_v8f<<<grid, 128>>>(ids2, emb, out, n_tokens);
}

// round 12
// speedup vs baseline: 1.0257x; 1.0257x over previous
#include <cuda_runtime.h>
#include <cstdint>

// Embedding gather: out[token, :] = embedding[input_ids[token], :]
// input_ids: [4096] i32, embedding: [32000,1024] f32, out: [4096,1024] f32
//
// Converged configuration (best of an 11-round sweep over block size, tokens
// per CTA, MLP depth, memory-op width, TMA/bulk engines, and cache hints):
//   - 1024 CTAs x 256 threads: single resident wave (<=148 SMs x 8), no
//     wave transitions.
//   - 4 tokens per CTA; all 4 ids fetched in ONE int4 (16 B) broadcast load
//     so the dependent id->row chain head is a single transaction.
//   - 4 independent float4 row loads per thread (different rows, true MLP=4),
//     plain C++ ld/st (ptxas's 24-reg schedule measured fastest).
// All variants land within noise of the ~8.5 us latency/ramp floor for this
// 33 MB gather; no ncu pipe exceeds 25% utilization.

static constexpr int ROW_F4         = 256;  // float4 per 4 KB row
static constexpr int TOKENS_PER_CTA = 4;

__global__ void __launch_bounds__(256)
embed_gather_kernel(const int4* __restrict__ ids4,
                    const float4* __restrict__ emb,
                    float4* __restrict__ out,
                    int n_tokens)
{
    const int tid  = threadIdx.x;
    const int base = blockIdx.x * TOKENS_PER_CTA;

    // One 16-byte load fetches all 4 token ids (broadcast across the CTA).
    int4 id = ids4[blockIdx.x];

    // 4 independent row loads (different rows -> true MLP=4).
    float4 v0 = emb[(size_t)id.x * ROW_F4 + tid];
    float4 v1 = emb[(size_t)id.y * ROW_F4 + tid];
    float4 v2 = emb[(size_t)id.z * ROW_F4 + tid];
    float4 v3 = emb[(size_t)id.w * ROW_F4 + tid];

    float4* dst = out + (size_t)base * ROW_F4 + tid;
    dst[0 * ROW_F4] = v0;
    dst[1 * ROW_F4] = v1;
    dst[2 * ROW_F4] = v2;
    dst[3 * ROW_F4] = v3;
}

extern "C" void kernel_launch(void* const* d_in, const int* in_sizes, int n_in,
                              void* d_out, int out_size)
{
    const int4*   ids4 = (const int4*)d_in[0];
    const float4* emb  = (const float4*)d_in[1];
    float4*       out  = (float4*)d_out;

    int n_tokens = in_sizes[0];               // 4096 (divisible by 4)
    int grid = n_tokens / TOKENS_PER_CTA;     // 1024 — single resident wave
    embed_gather_kernel<<<grid, 256>>>(ids4, emb, out, n_tokens);
}